// round 12
// baseline (speedup 1.0000x reference)
#include <cuda_runtime.h>
#include <cuda_bf16.h>
#include <cstdint>

// ---------------- problem sizes ----------------
#define TOKENS 8192
#define DMODEL 2048
#define DFF    8192

// ---------------- GEMM tiling (tensor pipe @96%, do not touch) ----------------
#define BM 128
#define BN 128
#define BK 64
#define STAGES 5
#define ROWB 80                         // 64B data + 16B pad: conflict-free ldmatrix
#define TILEB (128 * ROWB)              // 10240 B per operand tile
#define STAGE_BYTES (2 * TILEB)         // 20480 B
#define GEMM_SMEM (STAGES * STAGE_BYTES)// 102400 B -> 2 CTAs/SM

// ---------------- scratch (no allocations allowed) ----------------
__device__ int8_t   g_xq [(size_t)TOKENS * DMODEL];
__device__ int8_t   g_w1q[(size_t)DFF    * DMODEL];
__device__ int8_t   g_w2q[(size_t)DMODEL * DFF];
__device__ int8_t   g_hq [(size_t)TOKENS * DFF];
// 128 MB: uint16 relu(acc1) during G1/qh, then REUSED as 2x s32 split-K partials for G2
__device__ unsigned short g_ha[(size_t)TOKENS * DFF];
__device__ float    g_sx[TOKENS];                      // 127/absmax per token
__device__ float    g_d2[TOKENS];
__device__ int      g_rowmax[TOKENS];
__device__ double   g_sum[2];                          // zero-init; self-resetting
__device__ int      g_ctr[2];                          // zero-init; self-resetting
__device__ float    g_gamma[2];

// ---------------- PTX helpers ----------------
__device__ __forceinline__ uint32_t smem_u32(const void* p) {
    uint32_t a;
    asm("{ .reg .u64 t; cvta.to.shared.u64 t, %1; cvt.u32.u64 %0, t; }" : "=r"(a) : "l"(p));
    return a;
}
#define CPA16(s, g) \
    asm volatile("cp.async.cg.shared.global [%0], [%1], 16;" :: "r"(s), "l"(g))
#define CP_COMMIT() asm volatile("cp.async.commit_group;" ::: "memory")
#define CP_WAIT3()  asm volatile("cp.async.wait_group 3;" ::: "memory")
#define LDSM4(r0, r1, r2, r3, addr) \
    asm volatile("ldmatrix.sync.aligned.m8n8.x4.shared.b16 {%0,%1,%2,%3}, [%4];" \
                 : "=r"(r0), "=r"(r1), "=r"(r2), "=r"(r3) : "r"(addr))
#define MMA_S8(c, a, b) \
    asm volatile("mma.sync.aligned.m16n8k32.row.col.s32.s8.s8.s32 " \
                 "{%0,%1,%2,%3}, {%4,%5,%6,%7}, {%8,%9}, {%0,%1,%2,%3};" \
                 : "+r"((c)[0]), "+r"((c)[1]), "+r"((c)[2]), "+r"((c)[3]) \
                 : "r"((a)[0]), "r"((a)[1]), "r"((a)[2]), "r"((a)[3]), \
                   "r"((b)[0]), "r"((b)[1]))

// ---------------- aux kernels ----------------
__global__ void k_quantize_x(const float* __restrict__ x) {
    __shared__ float red[256];
    const int t = blockIdx.x;
    const float4* row = (const float4*)(x + (size_t)t * DMODEL);
    float m = 0.f;
    for (int i = threadIdx.x; i < DMODEL / 4; i += 256) {
        float4 v = row[i];
        m = fmaxf(m, fmaxf(fmaxf(fabsf(v.x), fabsf(v.y)), fmaxf(fabsf(v.z), fabsf(v.w))));
    }
    red[threadIdx.x] = m;
    __syncthreads();
    for (int o = 128; o > 0; o >>= 1) {
        if (threadIdx.x < o) red[threadIdx.x] = fmaxf(red[threadIdx.x], red[threadIdx.x + o]);
        __syncthreads();
    }
    const float s = 127.0f / fmaxf(red[0], 1e-5f);
    char4* dst = (char4*)(g_xq + (size_t)t * DMODEL);
    for (int i = threadIdx.x; i < DMODEL / 4; i += 256) {
        float4 v = row[i];
        float q0 = fminf(fmaxf(rintf(v.x * s), -128.f), 127.f);
        float q1 = fminf(fmaxf(rintf(v.y * s), -128.f), 127.f);
        float q2 = fminf(fmaxf(rintf(v.z * s), -128.f), 127.f);
        float q3 = fminf(fmaxf(rintf(v.w * s), -128.f), 127.f);
        dst[i] = make_char4((char)(int)q0, (char)(int)q1, (char)(int)q2, (char)(int)q3);
    }
    if (threadIdx.x == 0) { g_sx[t] = s; g_rowmax[t] = 0; }
}

// |w| mean for ONE weight; dual accumulators + 2048 blocks (latency-bound fix).
// Last block finalizes gamma and self-resets state for graph replay.
__global__ void k_absmean1(const float* __restrict__ w, int idx) {
    __shared__ double red[256];
    const float4* w4 = (const float4*)w;
    const size_t n4 = (size_t)DFF * DMODEL / 4;
    const size_t stride = (size_t)gridDim.x * 256;
    double s0 = 0.0, s1 = 0.0;
    size_t i = (size_t)blockIdx.x * 256 + threadIdx.x;
    for (; i + stride < n4; i += 2 * stride) {
        float4 v0 = w4[i], v1 = w4[i + stride];
        s0 += (double)((fabsf(v0.x) + fabsf(v0.y)) + (fabsf(v0.z) + fabsf(v0.w)));
        s1 += (double)((fabsf(v1.x) + fabsf(v1.y)) + (fabsf(v1.z) + fabsf(v1.w)));
    }
    if (i < n4) {
        float4 v = w4[i];
        s0 += (double)((fabsf(v.x) + fabsf(v.y)) + (fabsf(v.z) + fabsf(v.w)));
    }
    red[threadIdx.x] = s0 + s1;
    __syncthreads();
    for (int o = 128; o > 0; o >>= 1) {
        if (threadIdx.x < o) red[threadIdx.x] += red[threadIdx.x + o];
        __syncthreads();
    }
    if (threadIdx.x == 0) {
        atomicAdd(&g_sum[idx], red[0]);
        __threadfence();
        const int done = atomicAdd(&g_ctr[idx], 1);
        if (done == gridDim.x - 1) {
            const double n = (double)DFF * DMODEL;
            const float gam = (float)(g_sum[idx] / n) + 1e-5f;
            g_sum[idx] = 0.0;            // self-reset for next graph replay
            g_ctr[idx] = 0;
            __threadfence();
            g_gamma[idx] = gam;
        }
    }
}

__global__ void k_quantize_w(const float* __restrict__ w, int idx) {
    int8_t* dst = idx ? g_w2q : g_w1q;
    const float g = g_gamma[idx];
    const float4* w4 = (const float4*)w;
    char4* d4 = (char4*)dst;
    const size_t n4 = (size_t)DFF * DMODEL / 4;
    for (size_t i = (size_t)blockIdx.x * blockDim.x + threadIdx.x; i < n4;
         i += (size_t)gridDim.x * blockDim.x) {
        float4 v = w4[i];
        float t0 = fminf(fmaxf(rintf(v.x / g), -1.f), 1.f);
        float t1 = fminf(fmaxf(rintf(v.y / g), -1.f), 1.f);
        float t2 = fminf(fmaxf(rintf(v.z / g), -1.f), 1.f);
        float t3 = fminf(fmaxf(rintf(v.w / g), -1.f), 1.f);
        d4[i] = make_char4((char)(int)t0, (char)(int)t1, (char)(int)t2, (char)(int)t3);
    }
}

// requantize h: read uint16 relu(acc), emit int8 hq
__global__ void k_quantize_h() {
    const int t = blockIdx.x;
    const float d1 = g_gamma[0] / g_sx[t];
    const float hl = d1 * (float)g_rowmax[t];
    const float s2 = 127.0f / fmaxf(hl * hl, 1e-5f);
    const uint4* src = (const uint4*)(g_ha + (size_t)t * DFF);   // 8 ushorts per uint4
    uint2* dst = (uint2*)(g_hq + (size_t)t * DFF);               // 8 chars per uint2
    for (int i = threadIdx.x; i < DFF / 8; i += blockDim.x) {
        uint4 v = src[i];
        unsigned u[8] = { v.x & 0xFFFFu, v.x >> 16, v.y & 0xFFFFu, v.y >> 16,
                          v.z & 0xFFFFu, v.z >> 16, v.w & 0xFFFFu, v.w >> 16 };
        unsigned lo = 0, hi = 0;
        #pragma unroll
        for (int j = 0; j < 4; j++) {
            float a = (float)u[j] * d1;
            int q = (int)fminf(rintf(a * a * s2), 127.f);
            lo |= ((unsigned)q & 0xFFu) << (8 * j);
        }
        #pragma unroll
        for (int j = 0; j < 4; j++) {
            float a = (float)u[4 + j] * d1;
            int q = (int)fminf(rintf(a * a * s2), 127.f);
            hi |= ((unsigned)q & 0xFFu) << (8 * j);
        }
        dst[i] = make_uint2(lo, hi);
    }
    if (threadIdx.x == 0) g_d2[t] = g_gamma[1] / s2;
}

// split-K reduce: out[t,:] = (float)(p0 + p1) * d2[t]
__global__ void k_reduce_scale(const int* __restrict__ p, float* __restrict__ out) {
    const int t = blockIdx.x;
    const float s = g_d2[t];
    const int4* p0 = (const int4*)(p + (size_t)t * DMODEL);
    const int4* p1 = (const int4*)(p + (size_t)TOKENS * DMODEL + (size_t)t * DMODEL);
    float4* o = (float4*)(out + (size_t)t * DMODEL);
    for (int i = threadIdx.x; i < DMODEL / 4; i += blockDim.x) {
        int4 a = p0[i], b = p1[i];
        o[i] = make_float4((float)(a.x + b.x) * s, (float)(a.y + b.y) * s,
                           (float)(a.z + b.z) * s, (float)(a.w + b.w) * s);
    }
}

// ---------------- int8 tensor-core GEMM (unchanged mainloop; split-K via blockIdx.z) ----------------
// A row stride = ldA; this CTA covers K range [blockIdx.z*kChunks*BK, +kChunks*BK).
// MODE 1: min(relu(acc),65535) -> outU (u16) + atomicMax rowmax.
// MODE 0: raw s32 acc -> outP + blockIdx.z * TOKENS*DMODEL   (split-K partial).
template<int MODE>
__global__ void __launch_bounds__(256, 2) k_gemm(
    const int8_t* __restrict__ A, const int8_t* __restrict__ B,
    int ldA, int kChunks, int ldo,
    unsigned short* __restrict__ outU, int* __restrict__ outP,
    int* __restrict__ rowmax)
{
    extern __shared__ char smem[];
    const uint32_t sbase = smem_u32(smem);
    const int t = threadIdx.x;
    const int wid = t >> 5, lane = t & 31;
    const int wm = wid >> 2, wn = wid & 3;          // 2 x 4 warp grid
    const int mBase = blockIdx.y * BM, nBase = blockIdx.x * BN;
    const int kOff = blockIdx.z * kChunks * BK;

    int acc[4][4][4];
    #pragma unroll
    for (int i = 0; i < 4; i++)
        #pragma unroll
        for (int j = 0; j < 4; j++)
            #pragma unroll
            for (int r = 0; r < 4; r++) acc[i][j][r] = 0;

    const int lrow = lane & 7;
    const uint32_t aOff = (uint32_t)((lrow + ((lane >> 3) & 1) * 8) * ROWB + (lane >> 4) * 16);
    const uint32_t bOff = (uint32_t)((lrow + (lane >> 4) * 8) * ROWB + ((lane >> 3) & 1) * 16);

    const int ldrow = t >> 2, ldch = t & 3;
    auto load_stage = [&](int kt, int slot) {
        const uint32_t sA = sbase + slot * STAGE_BYTES;
        const int k0 = kOff + kt * BK + ldch * 16;
        #pragma unroll
        for (int i = 0; i < 2; i++) {
            int row = ldrow + i * 64;
            CPA16(sA + row * ROWB + ldch * 16,
                  A + (size_t)(mBase + row) * ldA + k0);
            CPA16(sA + TILEB + row * ROWB + ldch * 16,
                  B + (size_t)(nBase + row) * ldA + k0);
        }
        CP_COMMIT();
    };

    load_stage(0, 0);
    load_stage(1, 1);
    load_stage(2, 2);
    load_stage(3, 3);

    for (int kt = 0; kt < kChunks; kt++) {
        CP_WAIT3();
        __syncthreads();
        const int nk = kt + 4;
        if (nk < kChunks) load_stage(nk, nk % STAGES);
        else CP_COMMIT();

        const uint32_t sA = sbase + (kt % STAGES) * STAGE_BYTES;
        const uint32_t sB = sA + TILEB;
        #pragma unroll
        for (int ks = 0; ks < 2; ks++) {
            uint32_t a[4][4], b[4][2];
            #pragma unroll
            for (int mi = 0; mi < 4; mi++)
                LDSM4(a[mi][0], a[mi][1], a[mi][2], a[mi][3],
                      sA + (wm * 64 + mi * 16) * ROWB + aOff + ks * 32);
            #pragma unroll
            for (int hf = 0; hf < 2; hf++) {
                uint32_t r0, r1, r2, r3;
                LDSM4(r0, r1, r2, r3,
                      sB + (wn * 32 + hf * 16) * ROWB + bOff + ks * 32);
                b[hf * 2][0] = r0; b[hf * 2][1] = r1;
                b[hf * 2 + 1][0] = r2; b[hf * 2 + 1][1] = r3;
            }
            #pragma unroll
            for (int mi = 0; mi < 4; mi++)
                #pragma unroll
                for (int ni = 0; ni < 4; ni++)
                    MMA_S8(acc[mi][ni], a[mi], b[ni]);
        }
    }

    const size_t pbase = (size_t)blockIdx.z * ((size_t)TOKENS * DMODEL);
    #pragma unroll
    for (int mi = 0; mi < 4; mi++) {
        #pragma unroll
        for (int hf = 0; hf < 2; hf++) {
            const int row = mBase + wm * 64 + mi * 16 + hf * 8 + (lane >> 2);
            if (MODE == 1) {
                int rm = 0;
                #pragma unroll
                for (int ni = 0; ni < 4; ni++) {
                    int v0 = min(max(acc[mi][ni][hf * 2 + 0], 0), 65535);
                    int v1 = min(max(acc[mi][ni][hf * 2 + 1], 0), 65535);
                    rm = max(rm, max(v0, v1));
                    const int col = nBase + wn * 32 + ni * 8 + 2 * (lane & 3);
                    *(ushort2*)(outU + (size_t)row * ldo + col) =
                        make_ushort2((unsigned short)v0, (unsigned short)v1);
                }
                rm = max(rm, __shfl_xor_sync(0xffffffffu, rm, 1));
                rm = max(rm, __shfl_xor_sync(0xffffffffu, rm, 2));
                if ((lane & 3) == 0) atomicMax(&rowmax[row], rm);
            } else {
                #pragma unroll
                for (int ni = 0; ni < 4; ni++) {
                    const int col = nBase + wn * 32 + ni * 8 + 2 * (lane & 3);
                    *(int2*)(outP + pbase + (size_t)row * ldo + col) =
                        make_int2(acc[mi][ni][hf * 2 + 0], acc[mi][ni][hf * 2 + 1]);
                }
            }
        }
    }
}

// ---------------- host ----------------
extern "C" void kernel_launch(void* const* d_in, const int* in_sizes, int n_in,
                              void* d_out, int out_size) {
    const float* x  = (const float*)d_in[0];
    const float* w1 = (const float*)d_in[1];
    const float* w2 = (const float*)d_in[2];
    float* out = (float*)d_out;

    void *p_xq, *p_w1q, *p_w2q, *p_hq, *p_ha, *p_rm;
    cudaGetSymbolAddress(&p_xq,  g_xq);
    cudaGetSymbolAddress(&p_w1q, g_w1q);
    cudaGetSymbolAddress(&p_w2q, g_w2q);
    cudaGetSymbolAddress(&p_hq,  g_hq);
    cudaGetSymbolAddress(&p_ha,  g_ha);
    cudaGetSymbolAddress(&p_rm,  g_rowmax);

    cudaFuncSetAttribute(k_gemm<1>, cudaFuncAttributeMaxDynamicSharedMemorySize, GEMM_SMEM);
    cudaFuncSetAttribute(k_gemm<0>, cudaFuncAttributeMaxDynamicSharedMemorySize, GEMM_SMEM);

    cudaStream_t s2;
    cudaStreamCreateWithFlags(&s2, cudaStreamNonBlocking);
    cudaEvent_t evFork, evW1, evW2;
    cudaEventCreateWithFlags(&evFork, cudaEventDisableTiming);
    cudaEventCreateWithFlags(&evW1,   cudaEventDisableTiming);
    cudaEventCreateWithFlags(&evW2,   cudaEventDisableTiming);

    cudaEventRecord(evFork, 0);
    cudaStreamWaitEvent(s2, evFork, 0);

    k_quantize_x<<<TOKENS, 256>>>(x);                               // s0

    // s2: w1 chain gates GEMM1; w2 chain overlaps GEMM1
    k_absmean1<<<2048, 256, 0, s2>>>(w1, 0);
    k_quantize_w<<<4096, 256, 0, s2>>>(w1, 0);
    cudaEventRecord(evW1, s2);
    k_absmean1<<<2048, 256, 0, s2>>>(w2, 1);
    k_quantize_w<<<4096, 256, 0, s2>>>(w2, 1);
    cudaEventRecord(evW2, s2);

    cudaStreamWaitEvent(0, evW1, 0);
    dim3 g1(DFF / BN, TOKENS / BM, 1);                              // 64 x 64
    k_gemm<1><<<g1, 256, GEMM_SMEM>>>((const int8_t*)p_xq, (const int8_t*)p_w1q,
                                      DMODEL, DMODEL / BK, DFF,
                                      (unsigned short*)p_ha, nullptr, (int*)p_rm);

    cudaStreamWaitEvent(0, evW2, 0);   // gamma[1] needed for d2
    k_quantize_h<<<TOKENS, 256>>>();   // consumes g_ha (same stream: done before G2 overwrites)

    dim3 g2(DMODEL / BN, TOKENS / BM, 2);                           // 16 x 64 x 2 = 2048 CTAs
    k_gemm<0><<<g2, 256, GEMM_SMEM>>>((const int8_t*)p_hq, (const int8_t*)p_w2q,
                                      DFF, (DFF / 2) / BK, DMODEL,
                                      nullptr, (int*)p_ha, nullptr);

    k_reduce_scale<<<TOKENS, 256>>>((const int*)p_ha, out);

    cudaEventDestroy(evFork);
    cudaEventDestroy(evW1);
    cudaEventDestroy(evW2);
    cudaStreamDestroy(s2);
}

// round 13
// speedup vs baseline: 1.0105x; 1.0105x over previous
#include <cuda_runtime.h>
#include <cuda_bf16.h>
#include <cstdint>

// ---------------- problem sizes ----------------
#define TOKENS 8192
#define DMODEL 2048
#define DFF    8192

// ---------------- GEMM tiling (tensor pipe @96%, frozen) ----------------
#define BM 128
#define BN 128
#define BK 64
#define STAGES 5
#define ROWB 80                         // 64B data + 16B pad: conflict-free ldmatrix
#define TILEB (128 * ROWB)              // 10240 B per operand tile
#define STAGE_BYTES (2 * TILEB)         // 20480 B
#define GEMM_SMEM (STAGES * STAGE_BYTES)// 102400 B -> 2 CTAs/SM

// ---------------- scratch (no allocations allowed) ----------------
__device__ int8_t   g_xq [(size_t)TOKENS * DMODEL];
__device__ int8_t   g_w1q[(size_t)DFF    * DMODEL];
__device__ int8_t   g_w2q[(size_t)DMODEL * DFF];
__device__ int8_t   g_hq [(size_t)TOKENS * DFF];
__device__ unsigned short g_ha[(size_t)TOKENS * DFF];  // relu(acc1), exact (<=65535 clamp)
__device__ float    g_sx[TOKENS];                      // 127/absmax per token
__device__ float    g_d2[TOKENS];
__device__ int      g_rowmax[TOKENS];
__device__ double   g_sum[2];                          // zero-init; self-resetting
__device__ int      g_ctr[2];                          // zero-init; self-resetting
__device__ float    g_gamma[2];

// ---------------- PTX helpers ----------------
__device__ __forceinline__ uint32_t smem_u32(const void* p) {
    uint32_t a;
    asm("{ .reg .u64 t; cvta.to.shared.u64 t, %1; cvt.u32.u64 %0, t; }" : "=r"(a) : "l"(p));
    return a;
}
#define CPA16(s, g) \
    asm volatile("cp.async.cg.shared.global [%0], [%1], 16;" :: "r"(s), "l"(g))
#define CP_COMMIT() asm volatile("cp.async.commit_group;" ::: "memory")
#define CP_WAIT3()  asm volatile("cp.async.wait_group 3;" ::: "memory")
#define LDSM4(r0, r1, r2, r3, addr) \
    asm volatile("ldmatrix.sync.aligned.m8n8.x4.shared.b16 {%0,%1,%2,%3}, [%4];" \
                 : "=r"(r0), "=r"(r1), "=r"(r2), "=r"(r3) : "r"(addr))
#define MMA_S8(c, a, b) \
    asm volatile("mma.sync.aligned.m16n8k32.row.col.s32.s8.s8.s32 " \
                 "{%0,%1,%2,%3}, {%4,%5,%6,%7}, {%8,%9}, {%0,%1,%2,%3};" \
                 : "+r"((c)[0]), "+r"((c)[1]), "+r"((c)[2]), "+r"((c)[3]) \
                 : "r"((a)[0]), "r"((a)[1]), "r"((a)[2]), "r"((a)[3]), \
                   "r"((b)[0]), "r"((b)[1]))

// ---------------- aux kernels ----------------
__global__ void k_quantize_x(const float* __restrict__ x) {
    __shared__ float red[256];
    const int t = blockIdx.x;
    const float4* row = (const float4*)(x + (size_t)t * DMODEL);
    float m = 0.f;
    for (int i = threadIdx.x; i < DMODEL / 4; i += 256) {
        float4 v = row[i];
        m = fmaxf(m, fmaxf(fmaxf(fabsf(v.x), fabsf(v.y)), fmaxf(fabsf(v.z), fabsf(v.w))));
    }
    red[threadIdx.x] = m;
    __syncthreads();
    for (int o = 128; o > 0; o >>= 1) {
        if (threadIdx.x < o) red[threadIdx.x] = fmaxf(red[threadIdx.x], red[threadIdx.x + o]);
        __syncthreads();
    }
    const float s = 127.0f / fmaxf(red[0], 1e-5f);
    char4* dst = (char4*)(g_xq + (size_t)t * DMODEL);
    for (int i = threadIdx.x; i < DMODEL / 4; i += 256) {
        float4 v = row[i];
        float q0 = fminf(fmaxf(rintf(v.x * s), -128.f), 127.f);
        float q1 = fminf(fmaxf(rintf(v.y * s), -128.f), 127.f);
        float q2 = fminf(fmaxf(rintf(v.z * s), -128.f), 127.f);
        float q3 = fminf(fmaxf(rintf(v.w * s), -128.f), 127.f);
        dst[i] = make_char4((char)(int)q0, (char)(int)q1, (char)(int)q2, (char)(int)q3);
    }
    if (threadIdx.x == 0) { g_sx[t] = s; g_rowmax[t] = 0; }
}

// |w| mean for ONE weight (R11 version, 1024 blocks measured-best);
// last block finalizes gamma and self-resets state for graph replay.
__global__ void k_absmean1(const float* __restrict__ w, int idx) {
    __shared__ double red[256];
    const float4* w4 = (const float4*)w;
    const size_t n4 = (size_t)DFF * DMODEL / 4;
    double s = 0.0;
    for (size_t i = (size_t)blockIdx.x * 256 + threadIdx.x; i < n4; i += (size_t)gridDim.x * 256) {
        float4 v = w4[i];
        s += (double)((fabsf(v.x) + fabsf(v.y)) + (fabsf(v.z) + fabsf(v.w)));
    }
    red[threadIdx.x] = s;
    __syncthreads();
    for (int o = 128; o > 0; o >>= 1) {
        if (threadIdx.x < o) red[threadIdx.x] += red[threadIdx.x + o];
        __syncthreads();
    }
    if (threadIdx.x == 0) {
        atomicAdd(&g_sum[idx], red[0]);
        __threadfence();
        const int done = atomicAdd(&g_ctr[idx], 1);
        if (done == gridDim.x - 1) {
            const double n = (double)DFF * DMODEL;
            const float gam = (float)(g_sum[idx] / n) + 1e-5f;
            g_sum[idx] = 0.0;            // self-reset for next graph replay
            g_ctr[idx] = 0;
            __threadfence();
            g_gamma[idx] = gam;
        }
    }
}

__global__ void k_quantize_w(const float* __restrict__ w, int idx) {
    int8_t* dst = idx ? g_w2q : g_w1q;
    const float g = g_gamma[idx];
    const float4* w4 = (const float4*)w;
    char4* d4 = (char4*)dst;
    const size_t n4 = (size_t)DFF * DMODEL / 4;
    for (size_t i = (size_t)blockIdx.x * blockDim.x + threadIdx.x; i < n4;
         i += (size_t)gridDim.x * blockDim.x) {
        float4 v = w4[i];
        float t0 = fminf(fmaxf(rintf(v.x / g), -1.f), 1.f);
        float t1 = fminf(fmaxf(rintf(v.y / g), -1.f), 1.f);
        float t2 = fminf(fmaxf(rintf(v.z / g), -1.f), 1.f);
        float t3 = fminf(fmaxf(rintf(v.w / g), -1.f), 1.f);
        d4[i] = make_char4((char)(int)t0, (char)(int)t1, (char)(int)t2, (char)(int)t3);
    }
}

// requantize h: streaming-read uint16 relu(acc), emit int8 hq
__global__ void k_quantize_h() {
    const int t = blockIdx.x;
    const float d1 = g_gamma[0] / g_sx[t];
    const float hl = d1 * (float)g_rowmax[t];
    const float s2 = 127.0f / fmaxf(hl * hl, 1e-5f);
    const uint4* src = (const uint4*)(g_ha + (size_t)t * DFF);   // 8 ushorts per uint4
    uint2* dst = (uint2*)(g_hq + (size_t)t * DFF);               // 8 chars per uint2
    for (int i = threadIdx.x; i < DFF / 8; i += blockDim.x) {
        uint4 v = __ldcs(&src[i]);       // single-use stream: don't pollute L2
        unsigned u[8] = { v.x & 0xFFFFu, v.x >> 16, v.y & 0xFFFFu, v.y >> 16,
                          v.z & 0xFFFFu, v.z >> 16, v.w & 0xFFFFu, v.w >> 16 };
        unsigned lo = 0, hi = 0;
        #pragma unroll
        for (int j = 0; j < 4; j++) {
            float a = (float)u[j] * d1;
            int q = (int)fminf(rintf(a * a * s2), 127.f);
            lo |= ((unsigned)q & 0xFFu) << (8 * j);
        }
        #pragma unroll
        for (int j = 0; j < 4; j++) {
            float a = (float)u[4 + j] * d1;
            int q = (int)fminf(rintf(a * a * s2), 127.f);
            hi |= ((unsigned)q & 0xFFu) << (8 * j);
        }
        dst[i] = make_uint2(lo, hi);
    }
    if (threadIdx.x == 0) g_d2[t] = g_gamma[1] / s2;
}

// ---------------- int8 tensor-core GEMM (frozen R5 mainloop) ----------------
// MODE 1: min(relu(acc),65535) -> outU (u16) + atomicMax rowmax.  MODE 0: acc*d2[row] -> outF.
template<int MODE>
__global__ void __launch_bounds__(256, 2) k_gemm(
    const int8_t* __restrict__ A, const int8_t* __restrict__ B,
    int K, int ldo,
    unsigned short* __restrict__ outU, float* __restrict__ outF,
    int* __restrict__ rowmax, const float* __restrict__ d2)
{
    extern __shared__ char smem[];
    const uint32_t sbase = smem_u32(smem);
    const int t = threadIdx.x;
    const int wid = t >> 5, lane = t & 31;
    const int wm = wid >> 2, wn = wid & 3;          // 2 x 4 warp grid
    const int mBase = blockIdx.y * BM, nBase = blockIdx.x * BN;
    const int kChunks = K / BK;

    int acc[4][4][4];
    #pragma unroll
    for (int i = 0; i < 4; i++)
        #pragma unroll
        for (int j = 0; j < 4; j++)
            #pragma unroll
            for (int r = 0; r < 4; r++) acc[i][j][r] = 0;

    const int lrow = lane & 7;
    const uint32_t aOff = (uint32_t)((lrow + ((lane >> 3) & 1) * 8) * ROWB + (lane >> 4) * 16);
    const uint32_t bOff = (uint32_t)((lrow + (lane >> 4) * 8) * ROWB + ((lane >> 3) & 1) * 16);

    const int ldrow = t >> 2, ldch = t & 3;
    auto load_stage = [&](int kt, int slot) {
        const uint32_t sA = sbase + slot * STAGE_BYTES;
        const int k0 = kt * BK + ldch * 16;
        #pragma unroll
        for (int i = 0; i < 2; i++) {
            int row = ldrow + i * 64;
            CPA16(sA + row * ROWB + ldch * 16,
                  A + (size_t)(mBase + row) * K + k0);
            CPA16(sA + TILEB + row * ROWB + ldch * 16,
                  B + (size_t)(nBase + row) * K + k0);
        }
        CP_COMMIT();
    };

    load_stage(0, 0);
    load_stage(1, 1);
    load_stage(2, 2);
    load_stage(3, 3);

    for (int kt = 0; kt < kChunks; kt++) {
        CP_WAIT3();
        __syncthreads();
        const int nk = kt + 4;
        if (nk < kChunks) load_stage(nk, nk % STAGES);
        else CP_COMMIT();

        const uint32_t sA = sbase + (kt % STAGES) * STAGE_BYTES;
        const uint32_t sB = sA + TILEB;
        #pragma unroll
        for (int ks = 0; ks < 2; ks++) {
            uint32_t a[4][4], b[4][2];
            #pragma unroll
            for (int mi = 0; mi < 4; mi++)
                LDSM4(a[mi][0], a[mi][1], a[mi][2], a[mi][3],
                      sA + (wm * 64 + mi * 16) * ROWB + aOff + ks * 32);
            #pragma unroll
            for (int hf = 0; hf < 2; hf++) {
                uint32_t r0, r1, r2, r3;
                LDSM4(r0, r1, r2, r3,
                      sB + (wn * 32 + hf * 16) * ROWB + bOff + ks * 32);
                b[hf * 2][0] = r0; b[hf * 2][1] = r1;
                b[hf * 2 + 1][0] = r2; b[hf * 2 + 1][1] = r3;
            }
            #pragma unroll
            for (int mi = 0; mi < 4; mi++)
                #pragma unroll
                for (int ni = 0; ni < 4; ni++)
                    MMA_S8(acc[mi][ni], a[mi], b[ni]);
        }
    }

    #pragma unroll
    for (int mi = 0; mi < 4; mi++) {
        #pragma unroll
        for (int hf = 0; hf < 2; hf++) {
            const int row = mBase + wm * 64 + mi * 16 + hf * 8 + (lane >> 2);
            if (MODE == 1) {
                int rm = 0;
                #pragma unroll
                for (int ni = 0; ni < 4; ni++) {
                    int v0 = min(max(acc[mi][ni][hf * 2 + 0], 0), 65535);
                    int v1 = min(max(acc[mi][ni][hf * 2 + 1], 0), 65535);
                    rm = max(rm, max(v0, v1));
                    const int col = nBase + wn * 32 + ni * 8 + 2 * (lane & 3);
                    *(ushort2*)(outU + (size_t)row * ldo + col) =
                        make_ushort2((unsigned short)v0, (unsigned short)v1);
                }
                rm = max(rm, __shfl_xor_sync(0xffffffffu, rm, 1));
                rm = max(rm, __shfl_xor_sync(0xffffffffu, rm, 2));
                if ((lane & 3) == 0) atomicMax(&rowmax[row], rm);
            } else {
                const float s = d2[row];
                #pragma unroll
                for (int ni = 0; ni < 4; ni++) {
                    float v0 = (float)acc[mi][ni][hf * 2 + 0] * s;
                    float v1 = (float)acc[mi][ni][hf * 2 + 1] * s;
                    const int col = nBase + wn * 32 + ni * 8 + 2 * (lane & 3);
                    *(float2*)(outF + (size_t)row * ldo + col) = make_float2(v0, v1);
                }
            }
        }
    }
}

// ---------------- host: R11 forked capture ----------------
extern "C" void kernel_launch(void* const* d_in, const int* in_sizes, int n_in,
                              void* d_out, int out_size) {
    const float* x  = (const float*)d_in[0];
    const float* w1 = (const float*)d_in[1];
    const float* w2 = (const float*)d_in[2];
    float* out = (float*)d_out;

    void *p_xq, *p_w1q, *p_w2q, *p_hq, *p_ha, *p_d2, *p_rm;
    cudaGetSymbolAddress(&p_xq,  g_xq);
    cudaGetSymbolAddress(&p_w1q, g_w1q);
    cudaGetSymbolAddress(&p_w2q, g_w2q);
    cudaGetSymbolAddress(&p_hq,  g_hq);
    cudaGetSymbolAddress(&p_ha,  g_ha);
    cudaGetSymbolAddress(&p_d2,  g_d2);
    cudaGetSymbolAddress(&p_rm,  g_rowmax);

    cudaFuncSetAttribute(k_gemm<1>, cudaFuncAttributeMaxDynamicSharedMemorySize, GEMM_SMEM);
    cudaFuncSetAttribute(k_gemm<0>, cudaFuncAttributeMaxDynamicSharedMemorySize, GEMM_SMEM);

    cudaStream_t s2;
    cudaStreamCreateWithFlags(&s2, cudaStreamNonBlocking);
    cudaEvent_t evFork, evW1, evW2;
    cudaEventCreateWithFlags(&evFork, cudaEventDisableTiming);
    cudaEventCreateWithFlags(&evW1,   cudaEventDisableTiming);
    cudaEventCreateWithFlags(&evW2,   cudaEventDisableTiming);

    cudaEventRecord(evFork, 0);
    cudaStreamWaitEvent(s2, evFork, 0);

    k_quantize_x<<<TOKENS, 256>>>(x);                               // s0

    // s2: w1 chain gates GEMM1; w2 chain overlaps GEMM1
    k_absmean1<<<1024, 256, 0, s2>>>(w1, 0);
    k_quantize_w<<<8192, 256, 0, s2>>>(w1, 0);
    cudaEventRecord(evW1, s2);
    k_absmean1<<<1024, 256, 0, s2>>>(w2, 1);
    k_quantize_w<<<8192, 256, 0, s2>>>(w2, 1);
    cudaEventRecord(evW2, s2);

    cudaStreamWaitEvent(0, evW1, 0);
    dim3 g1(DFF / BN, TOKENS / BM);                                 // 64 x 64
    k_gemm<1><<<g1, 256, GEMM_SMEM>>>((const int8_t*)p_xq, (const int8_t*)p_w1q,
                                      DMODEL, DFF,
                                      (unsigned short*)p_ha, nullptr, (int*)p_rm, nullptr);

    cudaStreamWaitEvent(0, evW2, 0);   // gamma[1] needed by k_quantize_h's d2
    k_quantize_h<<<TOKENS, 256>>>();

    dim3 g2(DMODEL / BN, TOKENS / BM);                              // 16 x 64
    k_gemm<0><<<g2, 256, GEMM_SMEM>>>((const int8_t*)p_hq, (const int8_t*)p_w2q,
                                      DFF, DMODEL,
                                      nullptr, out, nullptr, (const float*)p_d2);

    cudaEventDestroy(evFork);
    cudaEventDestroy(evW1);
    cudaEventDestroy(evW2);
    cudaStreamDestroy(s2);
}

// round 14
// speedup vs baseline: 1.0132x; 1.0027x over previous
#include <cuda_runtime.h>
#include <cuda_bf16.h>
#include <cstdint>

// ---------------- problem sizes ----------------
#define TOKENS 8192
#define DMODEL 2048
#define DFF    8192

// ---------------- GEMM tiling (tensor pipe @96%, frozen) ----------------
#define BM 128
#define BN 128
#define BK 64
#define STAGES 5
#define ROWB 80                         // 64B data + 16B pad: conflict-free ldmatrix
#define TILEB (128 * ROWB)              // 10240 B per operand tile
#define STAGE_BYTES (2 * TILEB)         // 20480 B
#define GEMM_SMEM (STAGES * STAGE_BYTES)// 102400 B -> 2 CTAs/SM

// ---------------- scratch (no allocations allowed) ----------------
__device__ int8_t   g_xq [(size_t)TOKENS * DMODEL];
__device__ int8_t   g_w1q[(size_t)DFF    * DMODEL];
__device__ int8_t   g_w2q[(size_t)DMODEL * DFF];
__device__ int8_t   g_hq [(size_t)TOKENS * DFF];
__device__ unsigned short g_ha[(size_t)TOKENS * DFF];  // relu(acc1), exact (<=65535 clamp)
__device__ float    g_sx[TOKENS];                      // 127/absmax per token
__device__ float    g_d2[TOKENS];
__device__ int      g_rowmax[TOKENS];
__device__ double   g_sum[2];                          // zero-init; self-resetting
__device__ int      g_ctr[2];                          // zero-init; self-resetting
__device__ float    g_gamma[2];

// ---------------- PTX helpers ----------------
__device__ __forceinline__ uint32_t smem_u32(const void* p) {
    uint32_t a;
    asm("{ .reg .u64 t; cvta.to.shared.u64 t, %1; cvt.u32.u64 %0, t; }" : "=r"(a) : "l"(p));
    return a;
}
#define CPA16(s, g) \
    asm volatile("cp.async.cg.shared.global [%0], [%1], 16;" :: "r"(s), "l"(g))
#define CP_COMMIT() asm volatile("cp.async.commit_group;" ::: "memory")
#define CP_WAIT3()  asm volatile("cp.async.wait_group 3;" ::: "memory")
#define LDSM4(r0, r1, r2, r3, addr) \
    asm volatile("ldmatrix.sync.aligned.m8n8.x4.shared.b16 {%0,%1,%2,%3}, [%4];" \
                 : "=r"(r0), "=r"(r1), "=r"(r2), "=r"(r3) : "r"(addr))
#define MMA_S8(c, a, b) \
    asm volatile("mma.sync.aligned.m16n8k32.row.col.s32.s8.s8.s32 " \
                 "{%0,%1,%2,%3}, {%4,%5,%6,%7}, {%8,%9}, {%0,%1,%2,%3};" \
                 : "+r"((c)[0]), "+r"((c)[1]), "+r"((c)[2]), "+r"((c)[3]) \
                 : "r"((a)[0]), "r"((a)[1]), "r"((a)[2]), "r"((a)[3]), \
                   "r"((b)[0]), "r"((b)[1]))

// ---------------- aux kernels ----------------
__global__ void k_quantize_x(const float* __restrict__ x) {
    __shared__ float red[256];
    const int t = blockIdx.x;
    const float4* row = (const float4*)(x + (size_t)t * DMODEL);
    float m = 0.f;
    for (int i = threadIdx.x; i < DMODEL / 4; i += 256) {
        float4 v = row[i];
        m = fmaxf(m, fmaxf(fmaxf(fabsf(v.x), fabsf(v.y)), fmaxf(fabsf(v.z), fabsf(v.w))));
    }
    red[threadIdx.x] = m;
    __syncthreads();
    for (int o = 128; o > 0; o >>= 1) {
        if (threadIdx.x < o) red[threadIdx.x] = fmaxf(red[threadIdx.x], red[threadIdx.x + o]);
        __syncthreads();
    }
    const float s = 127.0f / fmaxf(red[0], 1e-5f);
    char4* dst = (char4*)(g_xq + (size_t)t * DMODEL);
    for (int i = threadIdx.x; i < DMODEL / 4; i += 256) {
        float4 v = row[i];
        float q0 = fminf(fmaxf(rintf(v.x * s), -128.f), 127.f);
        float q1 = fminf(fmaxf(rintf(v.y * s), -128.f), 127.f);
        float q2 = fminf(fmaxf(rintf(v.z * s), -128.f), 127.f);
        float q3 = fminf(fmaxf(rintf(v.w * s), -128.f), 127.f);
        dst[i] = make_char4((char)(int)q0, (char)(int)q1, (char)(int)q2, (char)(int)q3);
    }
    if (threadIdx.x == 0) { g_sx[t] = s; g_rowmax[t] = 0; }
}

// |w| mean for ONE weight. Float chunk-accumulation breaks the serial DADD
// latency chain (16 -> 4 dependent double adds; gamma error ~2.5e-10 relative).
// Last block finalizes gamma and self-resets state for graph replay.
__global__ void __launch_bounds__(256) k_absmean1(const float* __restrict__ w, int idx) {
    __shared__ double red[256];
    const float4* w4 = (const float4*)w;
    const size_t n4 = (size_t)DFF * DMODEL / 4;          // 4M float4s
    const size_t stride = (size_t)gridDim.x * 256;       // 262144
    double s = 0.0;
    for (size_t i0 = (size_t)blockIdx.x * 256 + threadIdx.x; i0 < n4; i0 += 4 * stride) {
        float f = 0.f;
        #pragma unroll
        for (int j = 0; j < 4; j++) {
            size_t i = i0 + (size_t)j * stride;
            if (i < n4) {
                float4 v = w4[i];
                f += (fabsf(v.x) + fabsf(v.y)) + (fabsf(v.z) + fabsf(v.w));
            }
        }
        s += (double)f;
    }
    red[threadIdx.x] = s;
    __syncthreads();
    for (int o = 128; o > 0; o >>= 1) {
        if (threadIdx.x < o) red[threadIdx.x] += red[threadIdx.x + o];
        __syncthreads();
    }
    if (threadIdx.x == 0) {
        atomicAdd(&g_sum[idx], red[0]);
        __threadfence();
        const int done = atomicAdd(&g_ctr[idx], 1);
        if (done == gridDim.x - 1) {
            const double n = (double)DFF * DMODEL;
            const float gam = (float)(g_sum[idx] / n) + 1e-5f;
            g_sum[idx] = 0.0;            // self-reset for next graph replay
            g_ctr[idx] = 0;
            __threadfence();
            g_gamma[idx] = gam;
        }
    }
}

__global__ void k_quantize_w(const float* __restrict__ w, int idx) {
    int8_t* dst = idx ? g_w2q : g_w1q;
    const float g = g_gamma[idx];
    const float4* w4 = (const float4*)w;
    char4* d4 = (char4*)dst;
    const size_t n4 = (size_t)DFF * DMODEL / 4;
    for (size_t i = (size_t)blockIdx.x * blockDim.x + threadIdx.x; i < n4;
         i += (size_t)gridDim.x * blockDim.x) {
        float4 v = w4[i];
        float t0 = fminf(fmaxf(rintf(v.x / g), -1.f), 1.f);
        float t1 = fminf(fmaxf(rintf(v.y / g), -1.f), 1.f);
        float t2 = fminf(fmaxf(rintf(v.z / g), -1.f), 1.f);
        float t3 = fminf(fmaxf(rintf(v.w / g), -1.f), 1.f);
        d4[i] = make_char4((char)(int)t0, (char)(int)t1, (char)(int)t2, (char)(int)t3);
    }
}

// requantize h: streaming-read uint16 relu(acc), emit int8 hq
__global__ void k_quantize_h() {
    const int t = blockIdx.x;
    const float d1 = g_gamma[0] / g_sx[t];
    const float hl = d1 * (float)g_rowmax[t];
    const float s2 = 127.0f / fmaxf(hl * hl, 1e-5f);
    const uint4* src = (const uint4*)(g_ha + (size_t)t * DFF);   // 8 ushorts per uint4
    uint2* dst = (uint2*)(g_hq + (size_t)t * DFF);               // 8 chars per uint2
    for (int i = threadIdx.x; i < DFF / 8; i += blockDim.x) {
        uint4 v = __ldcs(&src[i]);       // single-use stream: don't pollute L2
        unsigned u[8] = { v.x & 0xFFFFu, v.x >> 16, v.y & 0xFFFFu, v.y >> 16,
                          v.z & 0xFFFFu, v.z >> 16, v.w & 0xFFFFu, v.w >> 16 };
        unsigned lo = 0, hi = 0;
        #pragma unroll
        for (int j = 0; j < 4; j++) {
            float a = (float)u[j] * d1;
            int q = (int)fminf(rintf(a * a * s2), 127.f);
            lo |= ((unsigned)q & 0xFFu) << (8 * j);
        }
        #pragma unroll
        for (int j = 0; j < 4; j++) {
            float a = (float)u[4 + j] * d1;
            int q = (int)fminf(rintf(a * a * s2), 127.f);
            hi |= ((unsigned)q & 0xFFu) << (8 * j);
        }
        dst[i] = make_uint2(lo, hi);
    }
    if (threadIdx.x == 0) g_d2[t] = g_gamma[1] / s2;
}

// ---------------- int8 tensor-core GEMM (frozen R5 mainloop) ----------------
// MODE 1: min(relu(acc),65535) -> outU (u16) + atomicMax rowmax.  MODE 0: acc*d2[row] -> outF.
template<int MODE>
__global__ void __launch_bounds__(256, 2) k_gemm(
    const int8_t* __restrict__ A, const int8_t* __restrict__ B,
    int K, int ldo,
    unsigned short* __restrict__ outU, float* __restrict__ outF,
    int* __restrict__ rowmax, const float* __restrict__ d2)
{
    extern __shared__ char smem[];
    const uint32_t sbase = smem_u32(smem);
    const int t = threadIdx.x;
    const int wid = t >> 5, lane = t & 31;
    const int wm = wid >> 2, wn = wid & 3;          // 2 x 4 warp grid
    const int mBase = blockIdx.y * BM, nBase = blockIdx.x * BN;
    const int kChunks = K / BK;

    int acc[4][4][4];
    #pragma unroll
    for (int i = 0; i < 4; i++)
        #pragma unroll
        for (int j = 0; j < 4; j++)
            #pragma unroll
            for (int r = 0; r < 4; r++) acc[i][j][r] = 0;

    const int lrow = lane & 7;
    const uint32_t aOff = (uint32_t)((lrow + ((lane >> 3) & 1) * 8) * ROWB + (lane >> 4) * 16);
    const uint32_t bOff = (uint32_t)((lrow + (lane >> 4) * 8) * ROWB + ((lane >> 3) & 1) * 16);

    const int ldrow = t >> 2, ldch = t & 3;
    auto load_stage = [&](int kt, int slot) {
        const uint32_t sA = sbase + slot * STAGE_BYTES;
        const int k0 = kt * BK + ldch * 16;
        #pragma unroll
        for (int i = 0; i < 2; i++) {
            int row = ldrow + i * 64;
            CPA16(sA + row * ROWB + ldch * 16,
                  A + (size_t)(mBase + row) * K + k0);
            CPA16(sA + TILEB + row * ROWB + ldch * 16,
                  B + (size_t)(nBase + row) * K + k0);
        }
        CP_COMMIT();
    };

    load_stage(0, 0);
    load_stage(1, 1);
    load_stage(2, 2);
    load_stage(3, 3);

    for (int kt = 0; kt < kChunks; kt++) {
        CP_WAIT3();
        __syncthreads();
        const int nk = kt + 4;
        if (nk < kChunks) load_stage(nk, nk % STAGES);
        else CP_COMMIT();

        const uint32_t sA = sbase + (kt % STAGES) * STAGE_BYTES;
        const uint32_t sB = sA + TILEB;
        #pragma unroll
        for (int ks = 0; ks < 2; ks++) {
            uint32_t a[4][4], b[4][2];
            #pragma unroll
            for (int mi = 0; mi < 4; mi++)
                LDSM4(a[mi][0], a[mi][1], a[mi][2], a[mi][3],
                      sA + (wm * 64 + mi * 16) * ROWB + aOff + ks * 32);
            #pragma unroll
            for (int hf = 0; hf < 2; hf++) {
                uint32_t r0, r1, r2, r3;
                LDSM4(r0, r1, r2, r3,
                      sB + (wn * 32 + hf * 16) * ROWB + bOff + ks * 32);
                b[hf * 2][0] = r0; b[hf * 2][1] = r1;
                b[hf * 2 + 1][0] = r2; b[hf * 2 + 1][1] = r3;
            }
            #pragma unroll
            for (int mi = 0; mi < 4; mi++)
                #pragma unroll
                for (int ni = 0; ni < 4; ni++)
                    MMA_S8(acc[mi][ni], a[mi], b[ni]);
        }
    }

    #pragma unroll
    for (int mi = 0; mi < 4; mi++) {
        #pragma unroll
        for (int hf = 0; hf < 2; hf++) {
            const int row = mBase + wm * 64 + mi * 16 + hf * 8 + (lane >> 2);
            if (MODE == 1) {
                int rm = 0;
                #pragma unroll
                for (int ni = 0; ni < 4; ni++) {
                    int v0 = min(max(acc[mi][ni][hf * 2 + 0], 0), 65535);
                    int v1 = min(max(acc[mi][ni][hf * 2 + 1], 0), 65535);
                    rm = max(rm, max(v0, v1));
                    const int col = nBase + wn * 32 + ni * 8 + 2 * (lane & 3);
                    *(ushort2*)(outU + (size_t)row * ldo + col) =
                        make_ushort2((unsigned short)v0, (unsigned short)v1);
                }
                rm = max(rm, __shfl_xor_sync(0xffffffffu, rm, 1));
                rm = max(rm, __shfl_xor_sync(0xffffffffu, rm, 2));
                if ((lane & 3) == 0) atomicMax(&rowmax[row], rm);
            } else {
                const float s = d2[row];
                #pragma unroll
                for (int ni = 0; ni < 4; ni++) {
                    float v0 = (float)acc[mi][ni][hf * 2 + 0] * s;
                    float v1 = (float)acc[mi][ni][hf * 2 + 1] * s;
                    const int col = nBase + wn * 32 + ni * 8 + 2 * (lane & 3);
                    *(float2*)(outF + (size_t)row * ldo + col) = make_float2(v0, v1);
                }
            }
        }
    }
}

// ---------------- host: R11/R13 forked capture ----------------
extern "C" void kernel_launch(void* const* d_in, const int* in_sizes, int n_in,
                              void* d_out, int out_size) {
    const float* x  = (const float*)d_in[0];
    const float* w1 = (const float*)d_in[1];
    const float* w2 = (const float*)d_in[2];
    float* out = (float*)d_out;

    void *p_xq, *p_w1q, *p_w2q, *p_hq, *p_ha, *p_d2, *p_rm;
    cudaGetSymbolAddress(&p_xq,  g_xq);
    cudaGetSymbolAddress(&p_w1q, g_w1q);
    cudaGetSymbolAddress(&p_w2q, g_w2q);
    cudaGetSymbolAddress(&p_hq,  g_hq);
    cudaGetSymbolAddress(&p_ha,  g_ha);
    cudaGetSymbolAddress(&p_d2,  g_d2);
    cudaGetSymbolAddress(&p_rm,  g_rowmax);

    cudaFuncSetAttribute(k_gemm<1>, cudaFuncAttributeMaxDynamicSharedMemorySize, GEMM_SMEM);
    cudaFuncSetAttribute(k_gemm<0>, cudaFuncAttributeMaxDynamicSharedMemorySize, GEMM_SMEM);

    cudaStream_t s2;
    cudaStreamCreateWithFlags(&s2, cudaStreamNonBlocking);
    cudaEvent_t evFork, evW1, evW2;
    cudaEventCreateWithFlags(&evFork, cudaEventDisableTiming);
    cudaEventCreateWithFlags(&evW1,   cudaEventDisableTiming);
    cudaEventCreateWithFlags(&evW2,   cudaEventDisableTiming);

    cudaEventRecord(evFork, 0);
    cudaStreamWaitEvent(s2, evFork, 0);

    k_quantize_x<<<TOKENS, 256>>>(x);                               // s0

    // s2: w1 chain gates GEMM1; w2 chain overlaps GEMM1
    k_absmean1<<<1024, 256, 0, s2>>>(w1, 0);
    k_quantize_w<<<8192, 256, 0, s2>>>(w1, 0);
    cudaEventRecord(evW1, s2);
    k_absmean1<<<1024, 256, 0, s2>>>(w2, 1);
    k_quantize_w<<<8192, 256, 0, s2>>>(w2, 1);
    cudaEventRecord(evW2, s2);

    cudaStreamWaitEvent(0, evW1, 0);
    dim3 g1(DFF / BN, TOKENS / BM);                                 // 64 x 64
    k_gemm<1><<<g1, 256, GEMM_SMEM>>>((const int8_t*)p_xq, (const int8_t*)p_w1q,
                                      DMODEL, DFF,
                                      (unsigned short*)p_ha, nullptr, (int*)p_rm, nullptr);

    cudaStreamWaitEvent(0, evW2, 0);   // gamma[1] needed by k_quantize_h's d2
    k_quantize_h<<<TOKENS, 256>>>();

    dim3 g2(DMODEL / BN, TOKENS / BM);                              // 16 x 64
    k_gemm<0><<<g2, 256, GEMM_SMEM>>>((const int8_t*)p_hq, (const int8_t*)p_w2q,
                                      DFF, DMODEL,
                                      nullptr, out, nullptr, (const float*)p_d2);

    cudaEventDestroy(evFork);
    cudaEventDestroy(evW1);
    cudaEventDestroy(evW2);
    cudaStreamDestroy(s2);
}

// round 15
// speedup vs baseline: 1.0154x; 1.0021x over previous
#include <cuda_runtime.h>
#include <cuda_bf16.h>
#include <cstdint>

// ---------------- problem sizes ----------------
#define TOKENS 8192
#define DMODEL 2048
#define DFF    8192

// ---------------- GEMM tiling (tensor pipe @96%, frozen) ----------------
#define BM 128
#define BN 128
#define BK 64
#define STAGES 5
#define ROWB 80                         // 64B data + 16B pad: conflict-free ldmatrix
#define TILEB (128 * ROWB)              // 10240 B per operand tile
#define STAGE_BYTES (2 * TILEB)         // 20480 B
#define GEMM_SMEM (STAGES * STAGE_BYTES)// 102400 B -> 2 CTAs/SM

// ---------------- scratch (no allocations allowed) ----------------
__device__ int8_t   g_xq [(size_t)TOKENS * DMODEL];
__device__ int8_t   g_w1q[(size_t)DFF    * DMODEL];
__device__ int8_t   g_w2q[(size_t)DMODEL * DFF];
__device__ int8_t   g_hq [(size_t)TOKENS * DFF];
__device__ unsigned short g_ha[(size_t)TOKENS * DFF];  // relu(acc1), exact (<=65535 clamp)
__device__ float    g_sx[TOKENS];                      // 127/absmax per token
__device__ float    g_d2[TOKENS];
__device__ int      g_rowmax[TOKENS];
__device__ double   g_sum[2];                          // zero-init; self-resetting
__device__ int      g_ctr[2];                          // zero-init; self-resetting
__device__ float    g_gamma[2];

// ---------------- PTX helpers ----------------
__device__ __forceinline__ uint32_t smem_u32(const void* p) {
    uint32_t a;
    asm("{ .reg .u64 t; cvta.to.shared.u64 t, %1; cvt.u32.u64 %0, t; }" : "=r"(a) : "l"(p));
    return a;
}
#define CPA16(s, g) \
    asm volatile("cp.async.cg.shared.global [%0], [%1], 16;" :: "r"(s), "l"(g))
#define CP_COMMIT() asm volatile("cp.async.commit_group;" ::: "memory")
#define CP_WAIT3()  asm volatile("cp.async.wait_group 3;" ::: "memory")
#define LDSM4(r0, r1, r2, r3, addr) \
    asm volatile("ldmatrix.sync.aligned.m8n8.x4.shared.b16 {%0,%1,%2,%3}, [%4];" \
                 : "=r"(r0), "=r"(r1), "=r"(r2), "=r"(r3) : "r"(addr))
#define MMA_S8(c, a, b) \
    asm volatile("mma.sync.aligned.m16n8k32.row.col.s32.s8.s8.s32 " \
                 "{%0,%1,%2,%3}, {%4,%5,%6,%7}, {%8,%9}, {%0,%1,%2,%3};" \
                 : "+r"((c)[0]), "+r"((c)[1]), "+r"((c)[2]), "+r"((c)[3]) \
                 : "r"((a)[0]), "r"((a)[1]), "r"((a)[2]), "r"((a)[3]), \
                   "r"((b)[0]), "r"((b)[1]))

// ---------------- aux kernels ----------------
__global__ void k_quantize_x(const float* __restrict__ x) {
    __shared__ float red[256];
    const int t = blockIdx.x;
    const float4* row = (const float4*)(x + (size_t)t * DMODEL);
    float m = 0.f;
    for (int i = threadIdx.x; i < DMODEL / 4; i += 256) {
        float4 v = row[i];
        m = fmaxf(m, fmaxf(fmaxf(fabsf(v.x), fabsf(v.y)), fmaxf(fabsf(v.z), fabsf(v.w))));
    }
    red[threadIdx.x] = m;
    __syncthreads();
    for (int o = 128; o > 0; o >>= 1) {
        if (threadIdx.x < o) red[threadIdx.x] = fmaxf(red[threadIdx.x], red[threadIdx.x + o]);
        __syncthreads();
    }
    const float s = 127.0f / fmaxf(red[0], 1e-5f);
    char4* dst = (char4*)(g_xq + (size_t)t * DMODEL);
    for (int i = threadIdx.x; i < DMODEL / 4; i += 256) {
        float4 v = row[i];
        float q0 = fminf(fmaxf(rintf(v.x * s), -128.f), 127.f);
        float q1 = fminf(fmaxf(rintf(v.y * s), -128.f), 127.f);
        float q2 = fminf(fmaxf(rintf(v.z * s), -128.f), 127.f);
        float q3 = fminf(fmaxf(rintf(v.w * s), -128.f), 127.f);
        dst[i] = make_char4((char)(int)q0, (char)(int)q1, (char)(int)q2, (char)(int)q3);
    }
    if (threadIdx.x == 0) { g_sx[t] = s; g_rowmax[t] = 0; }
}

// |w| mean for ONE weight (R14: float chunk accumulation, latency-chain-free).
// Last block finalizes gamma and self-resets state for graph replay.
__global__ void __launch_bounds__(256) k_absmean1(const float* __restrict__ w, int idx) {
    __shared__ double red[256];
    const float4* w4 = (const float4*)w;
    const size_t n4 = (size_t)DFF * DMODEL / 4;          // 4M float4s
    const size_t stride = (size_t)gridDim.x * 256;
    double s = 0.0;
    for (size_t i0 = (size_t)blockIdx.x * 256 + threadIdx.x; i0 < n4; i0 += 4 * stride) {
        float f = 0.f;
        #pragma unroll
        for (int j = 0; j < 4; j++) {
            size_t i = i0 + (size_t)j * stride;
            if (i < n4) {
                float4 v = w4[i];
                f += (fabsf(v.x) + fabsf(v.y)) + (fabsf(v.z) + fabsf(v.w));
            }
        }
        s += (double)f;
    }
    red[threadIdx.x] = s;
    __syncthreads();
    for (int o = 128; o > 0; o >>= 1) {
        if (threadIdx.x < o) red[threadIdx.x] += red[threadIdx.x + o];
        __syncthreads();
    }
    if (threadIdx.x == 0) {
        atomicAdd(&g_sum[idx], red[0]);
        __threadfence();
        const int done = atomicAdd(&g_ctr[idx], 1);
        if (done == gridDim.x - 1) {
            const double n = (double)DFF * DMODEL;
            const float gam = (float)(g_sum[idx] / n) + 1e-5f;
            g_sum[idx] = 0.0;            // self-reset for next graph replay
            g_ctr[idx] = 0;
            __threadfence();
            g_gamma[idx] = gam;
        }
    }
}

// ternarize elements [i0, i1) of one weight (range-split for dual-stream overlap)
__global__ void k_quantize_w(const float* __restrict__ w, int idx, size_t i0, size_t i1) {
    int8_t* dst = idx ? g_w2q : g_w1q;
    const float g = g_gamma[idx];
    const float4* w4 = (const float4*)w;
    char4* d4 = (char4*)dst;
    for (size_t i = i0 + (size_t)blockIdx.x * blockDim.x + threadIdx.x; i < i1;
         i += (size_t)gridDim.x * blockDim.x) {
        float4 v = w4[i];
        float t0 = fminf(fmaxf(rintf(v.x / g), -1.f), 1.f);
        float t1 = fminf(fmaxf(rintf(v.y / g), -1.f), 1.f);
        float t2 = fminf(fmaxf(rintf(v.z / g), -1.f), 1.f);
        float t3 = fminf(fmaxf(rintf(v.w / g), -1.f), 1.f);
        d4[i] = make_char4((char)(int)t0, (char)(int)t1, (char)(int)t2, (char)(int)t3);
    }
}

// requantize h: streaming-read uint16 relu(acc), emit int8 hq
__global__ void k_quantize_h() {
    const int t = blockIdx.x;
    const float d1 = g_gamma[0] / g_sx[t];
    const float hl = d1 * (float)g_rowmax[t];
    const float s2 = 127.0f / fmaxf(hl * hl, 1e-5f);
    const uint4* src = (const uint4*)(g_ha + (size_t)t * DFF);   // 8 ushorts per uint4
    uint2* dst = (uint2*)(g_hq + (size_t)t * DFF);               // 8 chars per uint2
    for (int i = threadIdx.x; i < DFF / 8; i += blockDim.x) {
        uint4 v = __ldcs(&src[i]);       // single-use stream: don't pollute L2
        unsigned u[8] = { v.x & 0xFFFFu, v.x >> 16, v.y & 0xFFFFu, v.y >> 16,
                          v.z & 0xFFFFu, v.z >> 16, v.w & 0xFFFFu, v.w >> 16 };
        unsigned lo = 0, hi = 0;
        #pragma unroll
        for (int j = 0; j < 4; j++) {
            float a = (float)u[j] * d1;
            int q = (int)fminf(rintf(a * a * s2), 127.f);
            lo |= ((unsigned)q & 0xFFu) << (8 * j);
        }
        #pragma unroll
        for (int j = 0; j < 4; j++) {
            float a = (float)u[4 + j] * d1;
            int q = (int)fminf(rintf(a * a * s2), 127.f);
            hi |= ((unsigned)q & 0xFFu) << (8 * j);
        }
        dst[i] = make_uint2(lo, hi);
    }
    if (threadIdx.x == 0) g_d2[t] = g_gamma[1] / s2;
}

// ---------------- int8 tensor-core GEMM (frozen R5 mainloop) ----------------
// MODE 1: min(relu(acc),65535) -> outU (u16) + atomicMax rowmax.  MODE 0: acc*d2[row] -> outF.
template<int MODE>
__global__ void __launch_bounds__(256, 2) k_gemm(
    const int8_t* __restrict__ A, const int8_t* __restrict__ B,
    int K, int ldo,
    unsigned short* __restrict__ outU, float* __restrict__ outF,
    int* __restrict__ rowmax, const float* __restrict__ d2)
{
    extern __shared__ char smem[];
    const uint32_t sbase = smem_u32(smem);
    const int t = threadIdx.x;
    const int wid = t >> 5, lane = t & 31;
    const int wm = wid >> 2, wn = wid & 3;          // 2 x 4 warp grid
    const int mBase = blockIdx.y * BM, nBase = blockIdx.x * BN;
    const int kChunks = K / BK;

    int acc[4][4][4];
    #pragma unroll
    for (int i = 0; i < 4; i++)
        #pragma unroll
        for (int j = 0; j < 4; j++)
            #pragma unroll
            for (int r = 0; r < 4; r++) acc[i][j][r] = 0;

    const int lrow = lane & 7;
    const uint32_t aOff = (uint32_t)((lrow + ((lane >> 3) & 1) * 8) * ROWB + (lane >> 4) * 16);
    const uint32_t bOff = (uint32_t)((lrow + (lane >> 4) * 8) * ROWB + ((lane >> 3) & 1) * 16);

    const int ldrow = t >> 2, ldch = t & 3;
    auto load_stage = [&](int kt, int slot) {
        const uint32_t sA = sbase + slot * STAGE_BYTES;
        const int k0 = kt * BK + ldch * 16;
        #pragma unroll
        for (int i = 0; i < 2; i++) {
            int row = ldrow + i * 64;
            CPA16(sA + row * ROWB + ldch * 16,
                  A + (size_t)(mBase + row) * K + k0);
            CPA16(sA + TILEB + row * ROWB + ldch * 16,
                  B + (size_t)(nBase + row) * K + k0);
        }
        CP_COMMIT();
    };

    load_stage(0, 0);
    load_stage(1, 1);
    load_stage(2, 2);
    load_stage(3, 3);

    for (int kt = 0; kt < kChunks; kt++) {
        CP_WAIT3();
        __syncthreads();
        const int nk = kt + 4;
        if (nk < kChunks) load_stage(nk, nk % STAGES);
        else CP_COMMIT();

        const uint32_t sA = sbase + (kt % STAGES) * STAGE_BYTES;
        const uint32_t sB = sA + TILEB;
        #pragma unroll
        for (int ks = 0; ks < 2; ks++) {
            uint32_t a[4][4], b[4][2];
            #pragma unroll
            for (int mi = 0; mi < 4; mi++)
                LDSM4(a[mi][0], a[mi][1], a[mi][2], a[mi][3],
                      sA + (wm * 64 + mi * 16) * ROWB + aOff + ks * 32);
            #pragma unroll
            for (int hf = 0; hf < 2; hf++) {
                uint32_t r0, r1, r2, r3;
                LDSM4(r0, r1, r2, r3,
                      sB + (wn * 32 + hf * 16) * ROWB + bOff + ks * 32);
                b[hf * 2][0] = r0; b[hf * 2][1] = r1;
                b[hf * 2 + 1][0] = r2; b[hf * 2 + 1][1] = r3;
            }
            #pragma unroll
            for (int mi = 0; mi < 4; mi++)
                #pragma unroll
                for (int ni = 0; ni < 4; ni++)
                    MMA_S8(acc[mi][ni], a[mi], b[ni]);
        }
    }

    #pragma unroll
    for (int mi = 0; mi < 4; mi++) {
        #pragma unroll
        for (int hf = 0; hf < 2; hf++) {
            const int row = mBase + wm * 64 + mi * 16 + hf * 8 + (lane >> 2);
            if (MODE == 1) {
                int rm = 0;
                #pragma unroll
                for (int ni = 0; ni < 4; ni++) {
                    int v0 = min(max(acc[mi][ni][hf * 2 + 0], 0), 65535);
                    int v1 = min(max(acc[mi][ni][hf * 2 + 1], 0), 65535);
                    rm = max(rm, max(v0, v1));
                    const int col = nBase + wn * 32 + ni * 8 + 2 * (lane & 3);
                    *(ushort2*)(outU + (size_t)row * ldo + col) =
                        make_ushort2((unsigned short)v0, (unsigned short)v1);
                }
                rm = max(rm, __shfl_xor_sync(0xffffffffu, rm, 1));
                rm = max(rm, __shfl_xor_sync(0xffffffffu, rm, 2));
                if ((lane & 3) == 0) atomicMax(&rowmax[row], rm);
            } else {
                const float s = d2[row];
                #pragma unroll
                for (int ni = 0; ni < 4; ni++) {
                    float v0 = (float)acc[mi][ni][hf * 2 + 0] * s;
                    float v1 = (float)acc[mi][ni][hf * 2 + 1] * s;
                    const int col = nBase + wn * 32 + ni * 8 + 2 * (lane & 3);
                    *(float2*)(outF + (size_t)row * ldo + col) = make_float2(v0, v1);
                }
            }
        }
    }
}

// ---------------- host: forked capture, dual-stream w1 ternarize ----------------
extern "C" void kernel_launch(void* const* d_in, const int* in_sizes, int n_in,
                              void* d_out, int out_size) {
    const float* x  = (const float*)d_in[0];
    const float* w1 = (const float*)d_in[1];
    const float* w2 = (const float*)d_in[2];
    float* out = (float*)d_out;

    void *p_xq, *p_w1q, *p_w2q, *p_hq, *p_ha, *p_d2, *p_rm;
    cudaGetSymbolAddress(&p_xq,  g_xq);
    cudaGetSymbolAddress(&p_w1q, g_w1q);
    cudaGetSymbolAddress(&p_w2q, g_w2q);
    cudaGetSymbolAddress(&p_hq,  g_hq);
    cudaGetSymbolAddress(&p_ha,  g_ha);
    cudaGetSymbolAddress(&p_d2,  g_d2);
    cudaGetSymbolAddress(&p_rm,  g_rowmax);

    cudaFuncSetAttribute(k_gemm<1>, cudaFuncAttributeMaxDynamicSharedMemorySize, GEMM_SMEM);
    cudaFuncSetAttribute(k_gemm<0>, cudaFuncAttributeMaxDynamicSharedMemorySize, GEMM_SMEM);

    const size_t n4 = (size_t)DFF * DMODEL / 4;
    const size_t half = n4 / 2;

    cudaStream_t s2;
    cudaStreamCreateWithFlags(&s2, cudaStreamNonBlocking);
    cudaEvent_t evFork, evGam1, evW1h, evW2;
    cudaEventCreateWithFlags(&evFork, cudaEventDisableTiming);
    cudaEventCreateWithFlags(&evGam1, cudaEventDisableTiming);
    cudaEventCreateWithFlags(&evW1h,  cudaEventDisableTiming);
    cudaEventCreateWithFlags(&evW2,   cudaEventDisableTiming);

    cudaEventRecord(evFork, 0);
    cudaStreamWaitEvent(s2, evFork, 0);

    // s0: activations
    k_quantize_x<<<TOKENS, 256>>>(x);

    // s2: gamma(w1) -> first half ternarize
    k_absmean1<<<1024, 256, 0, s2>>>(w1, 0);
    cudaEventRecord(evGam1, s2);
    k_quantize_w<<<4096, 256, 0, s2>>>(w1, 0, 0, half);
    cudaEventRecord(evW1h, s2);
    // s2 continues with the w2 chain (overlaps GEMM1)
    k_absmean1<<<1024, 256, 0, s2>>>(w2, 1);
    k_quantize_w<<<8192, 256, 0, s2>>>(w2, 1, 0, n4);
    cudaEventRecord(evW2, s2);

    // s0: second half of w1 ternarize after qx (gamma ready via evGam1)
    cudaStreamWaitEvent(0, evGam1, 0);
    k_quantize_w<<<4096, 256>>>(w1, 0, half, n4);

    cudaStreamWaitEvent(0, evW1h, 0);   // first half done too
    dim3 g1(DFF / BN, TOKENS / BM);                                 // 64 x 64
    k_gemm<1><<<g1, 256, GEMM_SMEM>>>((const int8_t*)p_xq, (const int8_t*)p_w1q,
                                      DMODEL, DFF,
                                      (unsigned short*)p_ha, nullptr, (int*)p_rm, nullptr);

    cudaStreamWaitEvent(0, evW2, 0);    // gamma[1] needed by k_quantize_h's d2
    k_quantize_h<<<TOKENS, 256>>>();

    dim3 g2(DMODEL / BN, TOKENS / BM);                              // 16 x 64
    k_gemm<0><<<g2, 256, GEMM_SMEM>>>((const int8_t*)p_hq, (const int8_t*)p_w2q,
                                      DFF, DMODEL,
                                      nullptr, out, nullptr, (const float*)p_d2);

    cudaEventDestroy(evFork);
    cudaEventDestroy(evGam1);
    cudaEventDestroy(evW1h);
    cudaEventDestroy(evW2);
    cudaStreamDestroy(s2);
}

// round 16
// speedup vs baseline: 1.0175x; 1.0021x over previous
#include <cuda_runtime.h>
#include <cuda_bf16.h>
#include <cstdint>

// ---------------- problem sizes ----------------
#define TOKENS 8192
#define DMODEL 2048
#define DFF    8192

// ---------------- GEMM tiling (tensor pipe @96%, frozen) ----------------
#define BM 128
#define BN 128
#define BK 64
#define STAGES 5
#define ROWB 80                         // 64B data + 16B pad: conflict-free ldmatrix
#define TILEB (128 * ROWB)              // 10240 B per operand tile
#define STAGE_BYTES (2 * TILEB)         // 20480 B
#define GEMM_SMEM (STAGES * STAGE_BYTES)// 102400 B -> 2 CTAs/SM

// ---------------- scratch (no allocations allowed) ----------------
__device__ int8_t   g_xq [(size_t)TOKENS * DMODEL];
__device__ int8_t   g_w1q[(size_t)DFF    * DMODEL];
__device__ int8_t   g_w2q[(size_t)DMODEL * DFF];
__device__ int8_t   g_hq [(size_t)TOKENS * DFF];
__device__ unsigned short g_ha[(size_t)TOKENS * DFF];  // relu(acc1), exact (<=65535 clamp)
__device__ float    g_sx[TOKENS];                      // 127/absmax per token
__device__ float    g_d2[TOKENS];
__device__ int      g_rowmax[TOKENS];
__device__ double   g_sum[2];                          // zero-init; self-resetting
__device__ int      g_ctr[2];                          // zero-init; self-resetting
__device__ float    g_gamma[2];

// ---------------- PTX helpers ----------------
__device__ __forceinline__ uint32_t smem_u32(const void* p) {
    uint32_t a;
    asm("{ .reg .u64 t; cvta.to.shared.u64 t, %1; cvt.u32.u64 %0, t; }" : "=r"(a) : "l"(p));
    return a;
}
#define CPA16(s, g) \
    asm volatile("cp.async.cg.shared.global [%0], [%1], 16;" :: "r"(s), "l"(g))
#define CP_COMMIT() asm volatile("cp.async.commit_group;" ::: "memory")
#define CP_WAIT3()  asm volatile("cp.async.wait_group 3;" ::: "memory")
#define LDSM4(r0, r1, r2, r3, addr) \
    asm volatile("ldmatrix.sync.aligned.m8n8.x4.shared.b16 {%0,%1,%2,%3}, [%4];" \
                 : "=r"(r0), "=r"(r1), "=r"(r2), "=r"(r3) : "r"(addr))
#define MMA_S8(c, a, b) \
    asm volatile("mma.sync.aligned.m16n8k32.row.col.s32.s8.s8.s32 " \
                 "{%0,%1,%2,%3}, {%4,%5,%6,%7}, {%8,%9}, {%0,%1,%2,%3};" \
                 : "+r"((c)[0]), "+r"((c)[1]), "+r"((c)[2]), "+r"((c)[3]) \
                 : "r"((a)[0]), "r"((a)[1]), "r"((a)[2]), "r"((a)[3]), \
                   "r"((b)[0]), "r"((b)[1]))

// ---------------- aux kernels ----------------
// per-token absmax + int8 quantize; warp-shuffle reduction (1 barrier)
__global__ void k_quantize_x(const float* __restrict__ x) {
    __shared__ float wmax[8];
    const int t = blockIdx.x;
    const int lane = threadIdx.x & 31, wid = threadIdx.x >> 5;
    const float4* row = (const float4*)(x + (size_t)t * DMODEL);
    float m = 0.f;
    for (int i = threadIdx.x; i < DMODEL / 4; i += 256) {
        float4 v = row[i];
        m = fmaxf(m, fmaxf(fmaxf(fabsf(v.x), fabsf(v.y)), fmaxf(fabsf(v.z), fabsf(v.w))));
    }
    #pragma unroll
    for (int o = 16; o > 0; o >>= 1) m = fmaxf(m, __shfl_xor_sync(0xffffffffu, m, o));
    if (lane == 0) wmax[wid] = m;
    __syncthreads();
    float mm = wmax[0];
    #pragma unroll
    for (int j = 1; j < 8; j++) mm = fmaxf(mm, wmax[j]);
    const float s = 127.0f / fmaxf(mm, 1e-5f);
    char4* dst = (char4*)(g_xq + (size_t)t * DMODEL);
    for (int i = threadIdx.x; i < DMODEL / 4; i += 256) {
        float4 v = row[i];
        float q0 = fminf(fmaxf(rintf(v.x * s), -128.f), 127.f);
        float q1 = fminf(fmaxf(rintf(v.y * s), -128.f), 127.f);
        float q2 = fminf(fmaxf(rintf(v.z * s), -128.f), 127.f);
        float q3 = fminf(fmaxf(rintf(v.w * s), -128.f), 127.f);
        dst[i] = make_char4((char)(int)q0, (char)(int)q1, (char)(int)q2, (char)(int)q3);
    }
    if (threadIdx.x == 0) { g_sx[t] = s; g_rowmax[t] = 0; }
}

// |w| mean for ONE weight; float chunk accumulation + shuffle reduction (1 barrier).
// Last block finalizes gamma and self-resets state for graph replay.
__global__ void __launch_bounds__(256) k_absmean1(const float* __restrict__ w, int idx) {
    __shared__ double wsum[8];
    const int lane = threadIdx.x & 31, wid = threadIdx.x >> 5;
    const float4* w4 = (const float4*)w;
    const size_t n4 = (size_t)DFF * DMODEL / 4;
    const size_t stride = (size_t)gridDim.x * 256;
    double s = 0.0;
    for (size_t i0 = (size_t)blockIdx.x * 256 + threadIdx.x; i0 < n4; i0 += 4 * stride) {
        float f = 0.f;
        #pragma unroll
        for (int j = 0; j < 4; j++) {
            size_t i = i0 + (size_t)j * stride;
            if (i < n4) {
                float4 v = w4[i];
                f += (fabsf(v.x) + fabsf(v.y)) + (fabsf(v.z) + fabsf(v.w));
            }
        }
        s += (double)f;
    }
    #pragma unroll
    for (int o = 16; o > 0; o >>= 1) s += __shfl_xor_sync(0xffffffffu, s, o);
    if (lane == 0) wsum[wid] = s;
    __syncthreads();
    if (threadIdx.x == 0) {
        double tot = wsum[0];
        #pragma unroll
        for (int j = 1; j < 8; j++) tot += wsum[j];
        atomicAdd(&g_sum[idx], tot);
        __threadfence();
        const int done = atomicAdd(&g_ctr[idx], 1);
        if (done == gridDim.x - 1) {
            const double n = (double)DFF * DMODEL;
            const float gam = (float)(g_sum[idx] / n) + 1e-5f;
            g_sum[idx] = 0.0;            // self-reset for next graph replay
            g_ctr[idx] = 0;
            __threadfence();
            g_gamma[idx] = gam;
        }
    }
}

// ternarize elements [i0, i1) of one weight (range-split for dual-stream overlap)
__global__ void k_quantize_w(const float* __restrict__ w, int idx, size_t i0, size_t i1) {
    int8_t* dst = idx ? g_w2q : g_w1q;
    const float g = g_gamma[idx];
    const float4* w4 = (const float4*)w;
    char4* d4 = (char4*)dst;
    for (size_t i = i0 + (size_t)blockIdx.x * blockDim.x + threadIdx.x; i < i1;
         i += (size_t)gridDim.x * blockDim.x) {
        float4 v = w4[i];
        float t0 = fminf(fmaxf(rintf(v.x / g), -1.f), 1.f);
        float t1 = fminf(fmaxf(rintf(v.y / g), -1.f), 1.f);
        float t2 = fminf(fmaxf(rintf(v.z / g), -1.f), 1.f);
        float t3 = fminf(fmaxf(rintf(v.w / g), -1.f), 1.f);
        d4[i] = make_char4((char)(int)t0, (char)(int)t1, (char)(int)t2, (char)(int)t3);
    }
}

// requantize h: streaming-read uint16 relu(acc), emit int8 hq
__global__ void k_quantize_h() {
    const int t = blockIdx.x;
    const float d1 = g_gamma[0] / g_sx[t];
    const float hl = d1 * (float)g_rowmax[t];
    const float s2 = 127.0f / fmaxf(hl * hl, 1e-5f);
    const uint4* src = (const uint4*)(g_ha + (size_t)t * DFF);   // 8 ushorts per uint4
    uint2* dst = (uint2*)(g_hq + (size_t)t * DFF);               // 8 chars per uint2
    for (int i = threadIdx.x; i < DFF / 8; i += blockDim.x) {
        uint4 v = __ldcs(&src[i]);       // single-use stream: don't pollute L2
        unsigned u[8] = { v.x & 0xFFFFu, v.x >> 16, v.y & 0xFFFFu, v.y >> 16,
                          v.z & 0xFFFFu, v.z >> 16, v.w & 0xFFFFu, v.w >> 16 };
        unsigned lo = 0, hi = 0;
        #pragma unroll
        for (int j = 0; j < 4; j++) {
            float a = (float)u[j] * d1;
            int q = (int)fminf(rintf(a * a * s2), 127.f);
            lo |= ((unsigned)q & 0xFFu) << (8 * j);
        }
        #pragma unroll
        for (int j = 0; j < 4; j++) {
            float a = (float)u[4 + j] * d1;
            int q = (int)fminf(rintf(a * a * s2), 127.f);
            hi |= ((unsigned)q & 0xFFu) << (8 * j);
        }
        dst[i] = make_uint2(lo, hi);
    }
    if (threadIdx.x == 0) g_d2[t] = g_gamma[1] / s2;
}

// ---------------- int8 tensor-core GEMM (frozen R5 mainloop) ----------------
// MODE 1: min(relu(acc),65535) -> outU (u16) + atomicMax rowmax.  MODE 0: acc*d2[row] -> outF.
template<int MODE>
__global__ void __launch_bounds__(256, 2) k_gemm(
    const int8_t* __restrict__ A, const int8_t* __restrict__ B,
    int K, int ldo,
    unsigned short* __restrict__ outU, float* __restrict__ outF,
    int* __restrict__ rowmax, const float* __restrict__ d2)
{
    extern __shared__ char smem[];
    const uint32_t sbase = smem_u32(smem);
    const int t = threadIdx.x;
    const int wid = t >> 5, lane = t & 31;
    const int wm = wid >> 2, wn = wid & 3;          // 2 x 4 warp grid
    const int mBase = blockIdx.y * BM, nBase = blockIdx.x * BN;
    const int kChunks = K / BK;

    int acc[4][4][4];
    #pragma unroll
    for (int i = 0; i < 4; i++)
        #pragma unroll
        for (int j = 0; j < 4; j++)
            #pragma unroll
            for (int r = 0; r < 4; r++) acc[i][j][r] = 0;

    const int lrow = lane & 7;
    const uint32_t aOff = (uint32_t)((lrow + ((lane >> 3) & 1) * 8) * ROWB + (lane >> 4) * 16);
    const uint32_t bOff = (uint32_t)((lrow + (lane >> 4) * 8) * ROWB + ((lane >> 3) & 1) * 16);

    const int ldrow = t >> 2, ldch = t & 3;
    auto load_stage = [&](int kt, int slot) {
        const uint32_t sA = sbase + slot * STAGE_BYTES;
        const int k0 = kt * BK + ldch * 16;
        #pragma unroll
        for (int i = 0; i < 2; i++) {
            int row = ldrow + i * 64;
            CPA16(sA + row * ROWB + ldch * 16,
                  A + (size_t)(mBase + row) * K + k0);
            CPA16(sA + TILEB + row * ROWB + ldch * 16,
                  B + (size_t)(nBase + row) * K + k0);
        }
        CP_COMMIT();
    };

    load_stage(0, 0);
    load_stage(1, 1);
    load_stage(2, 2);
    load_stage(3, 3);

    for (int kt = 0; kt < kChunks; kt++) {
        CP_WAIT3();
        __syncthreads();
        const int nk = kt + 4;
        if (nk < kChunks) load_stage(nk, nk % STAGES);
        else CP_COMMIT();

        const uint32_t sA = sbase + (kt % STAGES) * STAGE_BYTES;
        const uint32_t sB = sA + TILEB;
        #pragma unroll
        for (int ks = 0; ks < 2; ks++) {
            uint32_t a[4][4], b[4][2];
            #pragma unroll
            for (int mi = 0; mi < 4; mi++)
                LDSM4(a[mi][0], a[mi][1], a[mi][2], a[mi][3],
                      sA + (wm * 64 + mi * 16) * ROWB + aOff + ks * 32);
            #pragma unroll
            for (int hf = 0; hf < 2; hf++) {
                uint32_t r0, r1, r2, r3;
                LDSM4(r0, r1, r2, r3,
                      sB + (wn * 32 + hf * 16) * ROWB + bOff + ks * 32);
                b[hf * 2][0] = r0; b[hf * 2][1] = r1;
                b[hf * 2 + 1][0] = r2; b[hf * 2 + 1][1] = r3;
            }
            #pragma unroll
            for (int mi = 0; mi < 4; mi++)
                #pragma unroll
                for (int ni = 0; ni < 4; ni++)
                    MMA_S8(acc[mi][ni], a[mi], b[ni]);
        }
    }

    #pragma unroll
    for (int mi = 0; mi < 4; mi++) {
        #pragma unroll
        for (int hf = 0; hf < 2; hf++) {
            const int row = mBase + wm * 64 + mi * 16 + hf * 8 + (lane >> 2);
            if (MODE == 1) {
                int rm = 0;
                #pragma unroll
                for (int ni = 0; ni < 4; ni++) {
                    int v0 = min(max(acc[mi][ni][hf * 2 + 0], 0), 65535);
                    int v1 = min(max(acc[mi][ni][hf * 2 + 1], 0), 65535);
                    rm = max(rm, max(v0, v1));
                    const int col = nBase + wn * 32 + ni * 8 + 2 * (lane & 3);
                    *(ushort2*)(outU + (size_t)row * ldo + col) =
                        make_ushort2((unsigned short)v0, (unsigned short)v1);
                }
                rm = max(rm, __shfl_xor_sync(0xffffffffu, rm, 1));
                rm = max(rm, __shfl_xor_sync(0xffffffffu, rm, 2));
                if ((lane & 3) == 0) atomicMax(&rowmax[row], rm);
            } else {
                const float s = d2[row];
                #pragma unroll
                for (int ni = 0; ni < 4; ni++) {
                    float v0 = (float)acc[mi][ni][hf * 2 + 0] * s;
                    float v1 = (float)acc[mi][ni][hf * 2 + 1] * s;
                    const int col = nBase + wn * 32 + ni * 8 + 2 * (lane & 3);
                    *(float2*)(outF + (size_t)row * ldo + col) = make_float2(v0, v1);
                }
            }
        }
    }
}

// ---------------- host: forked capture, dual-stream w1 ternarize ----------------
extern "C" void kernel_launch(void* const* d_in, const int* in_sizes, int n_in,
                              void* d_out, int out_size) {
    const float* x  = (const float*)d_in[0];
    const float* w1 = (const float*)d_in[1];
    const float* w2 = (const float*)d_in[2];
    float* out = (float*)d_out;

    void *p_xq, *p_w1q, *p_w2q, *p_hq, *p_ha, *p_d2, *p_rm;
    cudaGetSymbolAddress(&p_xq,  g_xq);
    cudaGetSymbolAddress(&p_w1q, g_w1q);
    cudaGetSymbolAddress(&p_w2q, g_w2q);
    cudaGetSymbolAddress(&p_hq,  g_hq);
    cudaGetSymbolAddress(&p_ha,  g_ha);
    cudaGetSymbolAddress(&p_d2,  g_d2);
    cudaGetSymbolAddress(&p_rm,  g_rowmax);

    cudaFuncSetAttribute(k_gemm<1>, cudaFuncAttributeMaxDynamicSharedMemorySize, GEMM_SMEM);
    cudaFuncSetAttribute(k_gemm<0>, cudaFuncAttributeMaxDynamicSharedMemorySize, GEMM_SMEM);

    const size_t n4 = (size_t)DFF * DMODEL / 4;
    const size_t half = n4 / 2;

    cudaStream_t s2;
    cudaStreamCreateWithFlags(&s2, cudaStreamNonBlocking);
    cudaEvent_t evFork, evGam1, evW1h, evW2;
    cudaEventCreateWithFlags(&evFork, cudaEventDisableTiming);
    cudaEventCreateWithFlags(&evGam1, cudaEventDisableTiming);
    cudaEventCreateWithFlags(&evW1h,  cudaEventDisableTiming);
    cudaEventCreateWithFlags(&evW2,   cudaEventDisableTiming);

    cudaEventRecord(evFork, 0);
    cudaStreamWaitEvent(s2, evFork, 0);

    // s0: activations
    k_quantize_x<<<TOKENS, 256>>>(x);

    // s2: gamma(w1) -> first half ternarize
    k_absmean1<<<1024, 256, 0, s2>>>(w1, 0);
    cudaEventRecord(evGam1, s2);
    k_quantize_w<<<4096, 256, 0, s2>>>(w1, 0, 0, half);
    cudaEventRecord(evW1h, s2);
    // s2 continues with the w2 chain (overlaps GEMM1)
    k_absmean1<<<1024, 256, 0, s2>>>(w2, 1);
    k_quantize_w<<<8192, 256, 0, s2>>>(w2, 1, 0, n4);
    cudaEventRecord(evW2, s2);

    // s0: second half of w1 ternarize after qx (gamma ready via evGam1)
    cudaStreamWaitEvent(0, evGam1, 0);
    k_quantize_w<<<4096, 256>>>(w1, 0, half, n4);

    cudaStreamWaitEvent(0, evW1h, 0);   // first half done too
    dim3 g1(DFF / BN, TOKENS / BM);                                 // 64 x 64
    k_gemm<1><<<g1, 256, GEMM_SMEM>>>((const int8_t*)p_xq, (const int8_t*)p_w1q,
                                      DMODEL, DFF,
                                      (unsigned short*)p_ha, nullptr, (int*)p_rm, nullptr);

    cudaStreamWaitEvent(0, evW2, 0);    // gamma[1] needed by k_quantize_h's d2
    k_quantize_h<<<TOKENS, 256>>>();

    dim3 g2(DMODEL / BN, TOKENS / BM);                              // 16 x 64
    k_gemm<0><<<g2, 256, GEMM_SMEM>>>((const int8_t*)p_hq, (const int8_t*)p_w2q,
                                      DFF, DMODEL,
                                      nullptr, out, nullptr, (const float*)p_d2);

    cudaEventDestroy(evFork);
    cudaEventDestroy(evGam1);
    cudaEventDestroy(evW1h);
    cudaEventDestroy(evW2);
    cudaStreamDestroy(s2);
}